// round 12
// baseline (speedup 1.0000x reference)
#include <cuda_runtime.h>
#include <cuda_fp16.h>
#include <cuda_bf16.h>

#define V_WORDS 50000
#define HD 128
#define N_DOCS 20000
#define E_CAP 1600000

typedef unsigned long long ull;

#define FFMA2(d, a, b, c) \
    asm("fma.rn.f32x2 %0, %1, %2, %3;" : "=l"(d) : "l"(a), "l"(b), "l"(c))
#define PACK2(d, f) \
    asm("mov.b64 %0, {%1, %1};" : "=l"(d) : "f"(f))
#define UNPACK2(lo, hi, v) \
    asm("mov.b64 {%0, %1}, %2;" : "=f"(lo), "=f"(hi) : "l"(v))

// Scratch (allocation-free rule: __device__ globals)
__device__ __nv_bfloat16 g_Ebf[V_WORDS * HD]; // E1 then T2 (bf16 gathered operands)
__device__ float  g_H1[V_WORDS * HD];          // H1 (fp32, dense-read by gemm)
__device__ __half g_Sh[V_WORDS * HD];          // S (fp16 gathered operand)
__device__ float  g_doc[N_DOCS * HD];
__device__ int2   g_Aed[E_CAP];
__device__ int2   g_Xed[E_CAP];
__device__ int    g_Arp[V_WORDS + 1];
__device__ int    g_Awp[V_WORDS];
__device__ int    g_Acnt[V_WORDS];
__device__ int    g_Xrp[N_DOCS + 1];
__device__ int    g_Xwp[N_DOCS];
__device__ int    g_Xcnt[N_DOCS];

// ---------------------------------------------------------------------------
// CSR build (A and X fused per phase)
// ---------------------------------------------------------------------------
__global__ void k_zero2(int* __restrict__ a, int na, int* __restrict__ b, int nb) {
    int i = blockIdx.x * blockDim.x + threadIdx.x;
    if (i < na) a[i] = 0;
    else if (i < na + nb) b[i - na] = 0;
}

__global__ void k_hist2(const int* __restrict__ rowA, int* __restrict__ cntA, int nA,
                        const int* __restrict__ rowX, int* __restrict__ cntX, int nX) {
    int i = blockIdx.x * blockDim.x + threadIdx.x;
    if (i < nA) atomicAdd(cntA + __ldg(rowA + i), 1);
    else if (i < nA + nX) atomicAdd(cntX + __ldg(rowX + (i - nA)), 1);
}

__device__ void scan_one(const int* __restrict__ cnt, int* __restrict__ rp,
                         int* __restrict__ wp, int n) {
    __shared__ int part[1024];
    int tid = threadIdx.x;
    int chunk = (n + 1023) >> 10;
    int beg = tid * chunk;
    int end = min(beg + chunk, n);
    int s = 0;
    for (int i = beg; i < end; i++) s += cnt[i];
    part[tid] = s;
    __syncthreads();
    for (int off = 1; off < 1024; off <<= 1) {
        int v = (tid >= off) ? part[tid - off] : 0;
        __syncthreads();
        part[tid] += v;
        __syncthreads();
    }
    int run = (tid == 0) ? 0 : part[tid - 1];
    for (int i = beg; i < end; i++) {
        int c = cnt[i];
        rp[i] = run;
        wp[i] = run;
        run += c;
    }
    if (tid == 1023) rp[n] = part[1023];
}

__global__ void k_scan2(const int* __restrict__ cntA, int* __restrict__ rpA,
                        int* __restrict__ wpA, int nA,
                        const int* __restrict__ cntX, int* __restrict__ rpX,
                        int* __restrict__ wpX, int nX) {
    if (blockIdx.x == 0) scan_one(cntA, rpA, wpA, nA);
    else                 scan_one(cntX, rpX, wpX, nX);
}

__global__ void k_scatter2(const int* __restrict__ rowA, const int* __restrict__ colA,
                           const float* __restrict__ valA, int* __restrict__ wpA,
                           int2* __restrict__ edA, int nA,
                           const int* __restrict__ rowX, const int* __restrict__ colX,
                           const float* __restrict__ valX, int* __restrict__ wpX,
                           int2* __restrict__ edX, int nX) {
    int i = blockIdx.x * blockDim.x + threadIdx.x;
    if (i < nA) {
        int r = __ldg(rowA + i);
        int p = atomicAdd(wpA + r, 1);
        edA[p] = make_int2(__ldg(colA + i), __float_as_int(__ldg(valA + i)));
    } else if (i < nA + nX) {
        int e = i - nA;
        int r = __ldg(rowX + e);
        int p = atomicAdd(wpX + r, 1);
        edX[p] = make_int2(__ldg(colX + e), __float_as_int(__ldg(valX + e)));
    }
}

// ---------------------------------------------------------------------------
// CSR SpMM, bf16 gather (cheap shift/AND up-convert), fp32 accum.
// One warp per output row; smem edge staging.
// MODE 1: relu -> float4 out (H1)
// MODE 2: relu->resid->LN->+emb -> fp16 out (S)
// ---------------------------------------------------------------------------
#define SPMM_BODY_BF(j)                                                     \
    {                                                                       \
        int2  m = es[w][(j)];                                               \
        float v = __int_as_float(m.y);                                      \
        uint2 u = __ldg(d2 + (size_t)m.x * 32 + lane);                      \
        float f0 = __int_as_float(u.x << 16);                               \
        float f1 = __int_as_float(u.x & 0xFFFF0000u);                       \
        float f2 = __int_as_float(u.y << 16);                               \
        float f3 = __int_as_float(u.y & 0xFFFF0000u);                       \
        acc.x = fmaf(v, f0, acc.x);                                         \
        acc.y = fmaf(v, f1, acc.y);                                         \
        acc.z = fmaf(v, f2, acc.z);                                         \
        acc.w = fmaf(v, f3, acc.w);                                         \
    }

template <int MODE>
__global__ void k_spmm_bf(const int* __restrict__ rp, const int2* __restrict__ ed,
                          const __nv_bfloat16* __restrict__ dense,
                          float* __restrict__ out, __half* __restrict__ outh, int nrows,
                          const float* __restrict__ emb,
                          const float* __restrict__ gw, const float* __restrict__ bw) {
    __shared__ int2 es[8][32];
    int wrow = (blockIdx.x * blockDim.x + threadIdx.x) >> 5;
    if (wrow >= nrows) return;
    int lane = threadIdx.x & 31;
    int w = (threadIdx.x >> 5) & 7;
    int start = __ldg(rp + wrow);
    int end   = __ldg(rp + wrow + 1);

    const uint2* d2 = reinterpret_cast<const uint2*>(dense);
    float4 acc = make_float4(0.f, 0.f, 0.f, 0.f);

    for (int base = start; base < end; base += 32) {
        int idx = base + lane;
        es[w][lane] = (idx < end) ? __ldg(ed + idx) : make_int2(0, 0);
        __syncwarp();
        int cnt = end - base;
        if (cnt >= 32) {
            #pragma unroll
            for (int j = 0; j < 32; j++) SPMM_BODY_BF(j)
        } else {
            for (int j = 0; j < cnt; j++) SPMM_BODY_BF(j)
        }
        __syncwarp();
    }

    // NOTE: lane's 4 values are interleaved (lo/hi pairs) but epilogues are
    // elementwise with per-lane layout; the layout is consistent between the
    // producer (bf16 pack order) and here. Producer packs (v0,v1) into one
    // 32-bit word as (lo=v0, hi=v1), so f0..f3 = cols (c0, c0+1, c0+2, c0+3)
    // matching the fp32 float4 layout exactly.
    if (MODE == 1) {
        float4 o = make_float4(fmaxf(acc.x, 0.f), fmaxf(acc.y, 0.f),
                               fmaxf(acc.z, 0.f), fmaxf(acc.w, 0.f));
        reinterpret_cast<float4*>(out)[(size_t)wrow * 32 + lane] = o;
    } else {
        float4 e4 = __ldg(reinterpret_cast<const float4*>(emb) + (size_t)wrow * 32 + lane);
        const float a = 0.7f, oma = 0.3f;
        float4 x;
        x.x = oma * e4.x + a * fmaxf(acc.x, 0.f);
        x.y = oma * e4.y + a * fmaxf(acc.y, 0.f);
        x.z = oma * e4.z + a * fmaxf(acc.z, 0.f);
        x.w = oma * e4.w + a * fmaxf(acc.w, 0.f);
        float s  = x.x + x.y + x.z + x.w;
        float sq = fmaf(x.x, x.x, fmaf(x.y, x.y, fmaf(x.z, x.z, x.w * x.w)));
        #pragma unroll
        for (int o = 16; o; o >>= 1) {
            s  += __shfl_xor_sync(0xFFFFFFFFu, s, o);
            sq += __shfl_xor_sync(0xFFFFFFFFu, sq, o);
        }
        float mu  = s * (1.0f / 128.0f);
        float var = sq * (1.0f / 128.0f) - mu * mu;
        float inv = rsqrtf(var + 1e-5f);
        float4 gv = __ldg(reinterpret_cast<const float4*>(gw) + lane);
        float4 bv = __ldg(reinterpret_cast<const float4*>(bw) + lane);
        float o0 = (x.x - mu) * inv * gv.x + bv.x + e4.x;
        float o1 = (x.y - mu) * inv * gv.y + bv.y + e4.y;
        float o2 = (x.z - mu) * inv * gv.z + bv.z + e4.z;
        float o3 = (x.w - mu) * inv * gv.w + bv.w + e4.w;
        __half2 p0 = __floats2half2_rn(o0, o1);
        __half2 p1 = __floats2half2_rn(o2, o3);
        uint2 u;
        u.x = *reinterpret_cast<unsigned*>(&p0);
        u.y = *reinterpret_cast<unsigned*>(&p1);
        reinterpret_cast<uint2*>(outh)[(size_t)wrow * 32 + lane] = u;
    }
}

// ---------------------------------------------------------------------------
// CSR SpMM, fp16 gather (doc pooling), fp32 accum/out, smem edge staging.
// ---------------------------------------------------------------------------
#define SPMM_BODY_HF(j)                                                     \
    {                                                                       \
        int2  m = es[w][(j)];                                               \
        float v = __int_as_float(m.y);                                      \
        uint2 u = __ldg(d2 + (size_t)m.x * 32 + lane);                      \
        __half2 h0 = *reinterpret_cast<__half2*>(&u.x);                     \
        __half2 h1 = *reinterpret_cast<__half2*>(&u.y);                     \
        float2 f0 = __half22float2(h0);                                     \
        float2 f1 = __half22float2(h1);                                     \
        acc.x = fmaf(v, f0.x, acc.x);                                       \
        acc.y = fmaf(v, f0.y, acc.y);                                       \
        acc.z = fmaf(v, f1.x, acc.z);                                       \
        acc.w = fmaf(v, f1.y, acc.w);                                       \
    }

__global__ void k_spmm_hf(const int* __restrict__ rp, const int2* __restrict__ ed,
                          const __half* __restrict__ dense, float* __restrict__ out,
                          int nrows) {
    __shared__ int2 es[8][32];
    int wrow = (blockIdx.x * blockDim.x + threadIdx.x) >> 5;
    if (wrow >= nrows) return;
    int lane = threadIdx.x & 31;
    int w = (threadIdx.x >> 5) & 7;
    int start = __ldg(rp + wrow);
    int end   = __ldg(rp + wrow + 1);

    const uint2* d2 = reinterpret_cast<const uint2*>(dense);
    float4 acc = make_float4(0.f, 0.f, 0.f, 0.f);

    for (int base = start; base < end; base += 32) {
        int idx = base + lane;
        es[w][lane] = (idx < end) ? __ldg(ed + idx) : make_int2(0, 0);
        __syncwarp();
        int cnt = end - base;
        if (cnt >= 32) {
            #pragma unroll
            for (int j = 0; j < 32; j++) SPMM_BODY_HF(j)
        } else {
            for (int j = 0; j < cnt; j++) SPMM_BODY_HF(j)
        }
        __syncwarp();
    }
    reinterpret_cast<float4*>(out)[(size_t)wrow * 32 + lane] = acc;
}

// ---------------------------------------------------------------------------
// GEMM: out = bf16(X @ W^T), f32x2 packed, 64-row tiles, W k-major in smem.
// bf16 pack: (v0,v1) -> word with lo=v0, hi=v1 (matches spmm up-convert order)
// ---------------------------------------------------------------------------
#define GEMM_BR 64
#define WPAD 130
#define XPAD 129

__device__ __forceinline__ unsigned pack_bf16x2(float lo, float hi) {
    __nv_bfloat162 p = __floats2bfloat162_rn(lo, hi);
    return *reinterpret_cast<unsigned*>(&p);
}

__global__ void k_gemm_bf(const float* __restrict__ X, const float* __restrict__ W,
                          __nv_bfloat16* __restrict__ outb, int R) {
    extern __shared__ float sm[];
    float* Wt = sm;                   // [128][WPAD], k-major
    float* Xs = sm + 128 * WPAD;      // [64][XPAD]
    int tid = threadIdx.x;

    for (int i = tid; i < 128 * 128; i += 256) {
        int c = i >> 7, k = i & 127;
        Wt[k * WPAD + c] = W[i];
    }
    int rb = blockIdx.x * GEMM_BR;
    for (int i = tid; i < GEMM_BR * 128; i += 256) {
        int r = i >> 7, k = i & 127;
        int gr = rb + r;
        Xs[r * XPAD + k] = (gr < R) ? X[(size_t)gr * HD + k] : 0.f;
    }
    __syncthreads();

    int tx = tid & 15, ty = tid >> 4;
    int r0 = ty * 4;
    int c0 = tx * 8;
    ull acc[4][4];
    #pragma unroll
    for (int i = 0; i < 4; i++)
        #pragma unroll
        for (int j = 0; j < 4; j++) acc[i][j] = 0ull;

    #pragma unroll 2
    for (int k = 0; k < 128; k++) {
        ull wv[4];
        #pragma unroll
        for (int jp = 0; jp < 4; jp++)
            wv[jp] = *reinterpret_cast<const ull*>(&Wt[k * WPAD + c0 + 2 * jp]);
        #pragma unroll
        for (int i = 0; i < 4; i++) {
            float xs = Xs[(r0 + i) * XPAD + k];
            ull xx;
            PACK2(xx, xs);
            #pragma unroll
            for (int jp = 0; jp < 4; jp++)
                FFMA2(acc[i][jp], xx, wv[jp], acc[i][jp]);
        }
    }

    #pragma unroll
    for (int i = 0; i < 4; i++) {
        int gr = rb + r0 + i;
        if (gr >= R) continue;
        float v[8];
        #pragma unroll
        for (int jp = 0; jp < 4; jp++) UNPACK2(v[2 * jp], v[2 * jp + 1], acc[i][jp]);
        uint4 u;
        u.x = pack_bf16x2(v[0], v[1]);
        u.y = pack_bf16x2(v[2], v[3]);
        u.z = pack_bf16x2(v[4], v[5]);
        u.w = pack_bf16x2(v[6], v[7]);
        *reinterpret_cast<uint4*>(outb + (size_t)gr * HD + c0) = u;
    }
}

// ---------------------------------------------------------------------------
// head: logits = relu(doc @ mlpW^T + mlpb) @ clfW^T + clfb   (f32x2 packed)
// ---------------------------------------------------------------------------
#define HPAD 130
__global__ void k_head(const float* __restrict__ doc, const float* __restrict__ mlpW,
                       const float* __restrict__ mlpb, const float* __restrict__ clfW,
                       const float* __restrict__ clfb, float* __restrict__ out) {
    extern __shared__ float sm[];
    float* Ws = sm;                       // [128][130]
    float* xs = Ws + 128 * HPAD;          // [128]
    float* mb = xs + 128;
    float* c0 = mb + 128;
    float* c1 = c0 + 128;
    __shared__ float red0[4], red1[4];

    int tid = threadIdx.x;
    for (int i = tid; i < 128 * 128; i += 128) {
        int r = i >> 7, k = i & 127;
        Ws[r * HPAD + k] = mlpW[i];
    }
    mb[tid] = mlpb[tid];
    c0[tid] = clfW[tid];
    c1[tid] = clfW[128 + tid];
    float cb0 = clfb[0], cb1 = clfb[1];
    __syncthreads();

    int lane = tid & 31, wid = tid >> 5;
    const ull* wrow = reinterpret_cast<const ull*>(&Ws[tid * HPAD]);
    for (int d = blockIdx.x; d < N_DOCS; d += gridDim.x) {
        xs[tid] = doc[(size_t)d * HD + tid];
        __syncthreads();
        ull acc2 = 0ull;
        const ull* x2 = reinterpret_cast<const ull*>(xs);
        #pragma unroll 8
        for (int kp = 0; kp < 64; kp++)
            FFMA2(acc2, x2[kp], wrow[kp], acc2);
        float alo, ahi;
        UNPACK2(alo, ahi, acc2);
        float h = fmaxf(alo + ahi + mb[tid], 0.f);
        float p0 = h * c0[tid];
        float p1 = h * c1[tid];
        #pragma unroll
        for (int o = 16; o; o >>= 1) {
            p0 += __shfl_down_sync(0xFFFFFFFFu, p0, o);
            p1 += __shfl_down_sync(0xFFFFFFFFu, p1, o);
        }
        if (lane == 0) { red0[wid] = p0; red1[wid] = p1; }
        __syncthreads();
        if (tid == 0) out[(size_t)d * 2]     = red0[0] + red0[1] + red0[2] + red0[3] + cb0;
        if (tid == 1) out[(size_t)d * 2 + 1] = red1[0] + red1[1] + red1[2] + red1[3] + cb1;
        __syncthreads();
    }
}

// ---------------------------------------------------------------------------
extern "C" void kernel_launch(void* const* d_in, const int* in_sizes, int n_in,
                              void* d_out, int out_size) {
    const int*   A_row  = (const int*)  d_in[0];
    const int*   A_col  = (const int*)  d_in[1];
    const float* A_val  = (const float*)d_in[2];
    const int*   X_row  = (const int*)  d_in[3];
    const int*   X_col  = (const int*)  d_in[4];
    const float* X_val  = (const float*)d_in[5];
    const float* emb_W  = (const float*)d_in[6];
    const float* lin1_W = (const float*)d_in[7];
    const float* lin2_W = (const float*)d_in[8];
    const float* norm_g = (const float*)d_in[9];
    const float* norm_b = (const float*)d_in[10];
    const float* mlp_W  = (const float*)d_in[11];
    const float* mlp_b  = (const float*)d_in[12];
    const float* clf_W  = (const float*)d_in[13];
    const float* clf_b  = (const float*)d_in[14];
    float* out = (float*)d_out;

    int E   = in_sizes[0];
    int NNZ = in_sizes[3];

    void *pEb, *pH1, *pSh, *pdoc, *pAed, *pXed, *pArp, *pAwp, *pAcnt, *pXrp, *pXwp, *pXcnt;
    cudaGetSymbolAddress(&pEb, g_Ebf);
    cudaGetSymbolAddress(&pH1, g_H1);
    cudaGetSymbolAddress(&pSh, g_Sh);
    cudaGetSymbolAddress(&pdoc, g_doc);
    cudaGetSymbolAddress(&pAed, g_Aed);
    cudaGetSymbolAddress(&pXed, g_Xed);
    cudaGetSymbolAddress(&pArp, g_Arp);
    cudaGetSymbolAddress(&pAwp, g_Awp);
    cudaGetSymbolAddress(&pAcnt, g_Acnt);
    cudaGetSymbolAddress(&pXrp, g_Xrp);
    cudaGetSymbolAddress(&pXwp, g_Xwp);
    cudaGetSymbolAddress(&pXcnt, g_Xcnt);
    __nv_bfloat16* Eb = (__nv_bfloat16*)pEb;
    float*  H1  = (float*)pH1;
    __half* Sh  = (__half*)pSh;
    float*  bd  = (float*)pdoc;
    int2* Aed = (int2*)pAed;
    int2* Xed = (int2*)pXed;
    int *Arp = (int*)pArp, *Awp = (int*)pAwp, *Acnt = (int*)pAcnt;
    int *Xrp = (int*)pXrp, *Xwp = (int*)pXwp, *Xcnt = (int*)pXcnt;

    const int gemm_smem = (128 * WPAD + GEMM_BR * XPAD) * sizeof(float);
    const int head_smem = (128 * HPAD + 4 * 128) * sizeof(float);
    cudaFuncSetAttribute(k_gemm_bf, cudaFuncAttributeMaxDynamicSharedMemorySize, gemm_smem);
    cudaFuncSetAttribute(k_head,    cudaFuncAttributeMaxDynamicSharedMemorySize, head_smem);

    const int both = E + NNZ;
    const int bg = (both + 255) / 256;
    const int spmmA_grid = (V_WORDS * 32 + 255) / 256;
    const int spmmX_grid = (N_DOCS * 32 + 255) / 256;
    const int gemm_grid  = (V_WORDS + GEMM_BR - 1) / GEMM_BR;

    // --- CSR builds ---
    k_zero2<<<(V_WORDS + N_DOCS + 255) / 256, 256>>>(Acnt, V_WORDS, Xcnt, N_DOCS);
    k_hist2<<<bg, 256>>>(A_row, Acnt, E, X_row, Xcnt, NNZ);
    k_scan2<<<2, 1024>>>(Acnt, Arp, Awp, V_WORDS, Xcnt, Xrp, Xwp, N_DOCS);
    k_scatter2<<<bg, 256>>>(A_row, A_col, A_val, Awp, Aed, E,
                            X_row, X_col, X_val, Xwp, Xed, NNZ);

    // E1 = bf16(emb @ lin1^T)   (hoist: relu(A@emb @ lin1^T) = relu(A @ E1))
    k_gemm_bf<<<gemm_grid, 256, gemm_smem>>>(emb_W, lin1_W, Eb, V_WORDS);
    // H1 = relu(A @ E1)         (bf16 gather via shift/AND, fp32 out)
    k_spmm_bf<1><<<spmmA_grid, 256>>>(Arp, Aed, Eb, H1, nullptr, V_WORDS,
                                      nullptr, nullptr, nullptr);
    // T2 = bf16(H1 @ lin2^T)
    k_gemm_bf<<<gemm_grid, 256, gemm_smem>>>(H1, lin2_W, Eb, V_WORDS);
    // Sh = fp16( LN(0.3*emb + 0.7*relu(A @ T2))*g + b + emb )
    k_spmm_bf<2><<<spmmA_grid, 256>>>(Arp, Aed, Eb, nullptr, Sh, V_WORDS,
                                      emb_W, norm_g, norm_b);
    // doc = X @ Sh              (fp16 gather, fp32 accum)
    k_spmm_hf<<<spmmX_grid, 256>>>(Xrp, Xed, Sh, bd, N_DOCS);
    // logits
    k_head<<<2000, 128, head_smem>>>(bd, mlp_W, mlp_b, clf_W, clf_b, out);
}

// round 15
// speedup vs baseline: 1.4639x; 1.4639x over previous
#include <cuda_runtime.h>
#include <cuda_fp16.h>

#define V_WORDS 50000
#define HD 128
#define N_DOCS 20000
#define E_CAP 1600000

typedef unsigned long long ull;

#define FFMA2(d, a, b, c) \
    asm("fma.rn.f32x2 %0, %1, %2, %3;" : "=l"(d) : "l"(a), "l"(b), "l"(c))
#define PACK2(d, f) \
    asm("mov.b64 %0, {%1, %1};" : "=l"(d) : "f"(f))
#define UNPACK2(lo, hi, v) \
    asm("mov.b64 {%0, %1}, %2;" : "=f"(lo), "=f"(hi) : "l"(v))

// Scratch (allocation-free rule: __device__ globals)
__device__ float  g_buf1[V_WORDS * HD];        // E1, later T2 (fp32 gathered operands)
__device__ float  g_buf2[V_WORDS * HD];        // H1
__device__ __half g_Sh[V_WORDS * HD];          // S (fp16 gathered operand)
__device__ float  g_doc[N_DOCS * HD];
__device__ int2   g_Aed[E_CAP];
__device__ int2   g_Xed[E_CAP];
__device__ int    g_Arp[V_WORDS + 1];
__device__ int    g_Awp[V_WORDS];
__device__ int    g_Acnt[V_WORDS];
__device__ int    g_Xrp[N_DOCS + 1];
__device__ int    g_Xwp[N_DOCS];
__device__ int    g_Xcnt[N_DOCS];

// ---------------------------------------------------------------------------
// CSR build (A and X fused per phase); hist & scatter do 4 edges/thread (MLP)
// ---------------------------------------------------------------------------
__global__ void k_zero2(int* __restrict__ a, int na, int* __restrict__ b, int nb) {
    int i = blockIdx.x * blockDim.x + threadIdx.x;
    if (i < na) a[i] = 0;
    else if (i < na + nb) b[i - na] = 0;
}

__device__ __forceinline__ void hist4(const int* __restrict__ row, int* __restrict__ cnt,
                                      int base, int n) {
    if (base + 3 < n) {
        int4 r = __ldg(reinterpret_cast<const int4*>(row + base));
        atomicAdd(cnt + r.x, 1);
        atomicAdd(cnt + r.y, 1);
        atomicAdd(cnt + r.z, 1);
        atomicAdd(cnt + r.w, 1);
    } else {
        for (int e = base; e < n; e++) atomicAdd(cnt + __ldg(row + e), 1);
    }
}

__global__ void k_hist2(const int* __restrict__ rowA, int* __restrict__ cntA, int nA4, int nA,
                        const int* __restrict__ rowX, int* __restrict__ cntX, int nX) {
    int t = blockIdx.x * blockDim.x + threadIdx.x;
    if (t < nA4) hist4(rowA, cntA, t * 4, nA);
    else         hist4(rowX, cntX, (t - nA4) * 4, nX);
}

__device__ void scan_one(const int* __restrict__ cnt, int* __restrict__ rp,
                         int* __restrict__ wp, int n) {
    __shared__ int part[1024];
    int tid = threadIdx.x;
    int chunk = (n + 1023) >> 10;
    int beg = tid * chunk;
    int end = min(beg + chunk, n);
    int s = 0;
    for (int i = beg; i < end; i++) s += cnt[i];
    part[tid] = s;
    __syncthreads();
    for (int off = 1; off < 1024; off <<= 1) {
        int v = (tid >= off) ? part[tid - off] : 0;
        __syncthreads();
        part[tid] += v;
        __syncthreads();
    }
    int run = (tid == 0) ? 0 : part[tid - 1];
    for (int i = beg; i < end; i++) {
        int c = cnt[i];
        rp[i] = run;
        wp[i] = run;
        run += c;
    }
    if (tid == 1023) rp[n] = part[1023];
}

__global__ void k_scan2(const int* __restrict__ cntA, int* __restrict__ rpA,
                        int* __restrict__ wpA, int nA,
                        const int* __restrict__ cntX, int* __restrict__ rpX,
                        int* __restrict__ wpX, int nX) {
    if (blockIdx.x == 0) scan_one(cntA, rpA, wpA, nA);
    else                 scan_one(cntX, rpX, wpX, nX);
}

__device__ __forceinline__ void scat4(const int* __restrict__ row, const int* __restrict__ col,
                                      const float* __restrict__ val, int* __restrict__ wp,
                                      int2* __restrict__ ed, int base, int n) {
    if (base + 3 < n) {
        int4   r = __ldg(reinterpret_cast<const int4*>(row + base));
        int4   c = __ldg(reinterpret_cast<const int4*>(col + base));
        float4 v = __ldg(reinterpret_cast<const float4*>(val + base));
        int p0 = atomicAdd(wp + r.x, 1);
        int p1 = atomicAdd(wp + r.y, 1);
        int p2 = atomicAdd(wp + r.z, 1);
        int p3 = atomicAdd(wp + r.w, 1);
        ed[p0] = make_int2(c.x, __float_as_int(v.x));
        ed[p1] = make_int2(c.y, __float_as_int(v.y));
        ed[p2] = make_int2(c.z, __float_as_int(v.z));
        ed[p3] = make_int2(c.w, __float_as_int(v.w));
    } else {
        for (int e = base; e < n; e++) {
            int p = atomicAdd(wp + __ldg(row + e), 1);
            ed[p] = make_int2(__ldg(col + e), __float_as_int(__ldg(val + e)));
        }
    }
}

__global__ void k_scatter2(const int* __restrict__ rowA, const int* __restrict__ colA,
                           const float* __restrict__ valA, int* __restrict__ wpA,
                           int2* __restrict__ edA, int nA4, int nA,
                           const int* __restrict__ rowX, const int* __restrict__ colX,
                           const float* __restrict__ valX, int* __restrict__ wpX,
                           int2* __restrict__ edX, int nX) {
    int t = blockIdx.x * blockDim.x + threadIdx.x;
    if (t < nA4) scat4(rowA, colA, valA, wpA, edA, t * 4, nA);
    else         scat4(rowX, colX, valX, wpX, edX, (t - nA4) * 4, nX);
}

// ---------------------------------------------------------------------------
// CSR SpMM, fp32 gather (LDG.128 — proven fast path), smem edge staging.
// MODE 1: relu -> float4 out (H1)
// MODE 2: relu->resid->LN->+emb -> fp16 out (S)
// ---------------------------------------------------------------------------
#define SPMM_BODY_F(j)                                                      \
    {                                                                       \
        int2  m = es[w][(j)];                                               \
        float v = __int_as_float(m.y);                                      \
        float4 x = __ldg(d4 + (size_t)m.x * 32 + lane);                     \
        acc.x = fmaf(v, x.x, acc.x);                                        \
        acc.y = fmaf(v, x.y, acc.y);                                        \
        acc.z = fmaf(v, x.z, acc.z);                                        \
        acc.w = fmaf(v, x.w, acc.w);                                        \
    }

template <int MODE>
__global__ void k_spmm_f(const int* __restrict__ rp, const int2* __restrict__ ed,
                         const float* __restrict__ dense, float* __restrict__ out,
                         __half* __restrict__ outh, int nrows,
                         const float* __restrict__ emb,
                         const float* __restrict__ gw, const float* __restrict__ bw) {
    __shared__ int2 es[8][32];
    int wrow = (blockIdx.x * blockDim.x + threadIdx.x) >> 5;
    if (wrow >= nrows) return;
    int lane = threadIdx.x & 31;
    int w = (threadIdx.x >> 5) & 7;
    int start = __ldg(rp + wrow);
    int end   = __ldg(rp + wrow + 1);

    const float4* d4 = reinterpret_cast<const float4*>(dense);
    float4 acc = make_float4(0.f, 0.f, 0.f, 0.f);

    for (int base = start; base < end; base += 32) {
        int idx = base + lane;
        es[w][lane] = (idx < end) ? __ldg(ed + idx) : make_int2(0, 0);
        __syncwarp();
        int cnt = end - base;
        if (cnt >= 32) {
            #pragma unroll
            for (int j = 0; j < 32; j++) SPMM_BODY_F(j)
        } else {
            for (int j = 0; j < cnt; j++) SPMM_BODY_F(j)
        }
        __syncwarp();
    }

    if (MODE == 1) {
        float4 o = make_float4(fmaxf(acc.x, 0.f), fmaxf(acc.y, 0.f),
                               fmaxf(acc.z, 0.f), fmaxf(acc.w, 0.f));
        reinterpret_cast<float4*>(out)[(size_t)wrow * 32 + lane] = o;
    } else {
        float4 e4 = __ldg(reinterpret_cast<const float4*>(emb) + (size_t)wrow * 32 + lane);
        const float a = 0.7f, oma = 0.3f;
        float4 x;
        x.x = oma * e4.x + a * fmaxf(acc.x, 0.f);
        x.y = oma * e4.y + a * fmaxf(acc.y, 0.f);
        x.z = oma * e4.z + a * fmaxf(acc.z, 0.f);
        x.w = oma * e4.w + a * fmaxf(acc.w, 0.f);
        float s  = x.x + x.y + x.z + x.w;
        float sq = fmaf(x.x, x.x, fmaf(x.y, x.y, fmaf(x.z, x.z, x.w * x.w)));
        #pragma unroll
        for (int o = 16; o; o >>= 1) {
            s  += __shfl_xor_sync(0xFFFFFFFFu, s, o);
            sq += __shfl_xor_sync(0xFFFFFFFFu, sq, o);
        }
        float mu  = s * (1.0f / 128.0f);
        float var = sq * (1.0f / 128.0f) - mu * mu;
        float inv = rsqrtf(var + 1e-5f);
        float4 gv = __ldg(reinterpret_cast<const float4*>(gw) + lane);
        float4 bv = __ldg(reinterpret_cast<const float4*>(bw) + lane);
        float o0 = (x.x - mu) * inv * gv.x + bv.x + e4.x;
        float o1 = (x.y - mu) * inv * gv.y + bv.y + e4.y;
        float o2 = (x.z - mu) * inv * gv.z + bv.z + e4.z;
        float o3 = (x.w - mu) * inv * gv.w + bv.w + e4.w;
        __half2 p0 = __floats2half2_rn(o0, o1);
        __half2 p1 = __floats2half2_rn(o2, o3);
        uint2 u;
        u.x = *reinterpret_cast<unsigned*>(&p0);
        u.y = *reinterpret_cast<unsigned*>(&p1);
        reinterpret_cast<uint2*>(outh)[(size_t)wrow * 32 + lane] = u;
    }
}

// ---------------------------------------------------------------------------
// CSR SpMM, fp16 gather (doc pooling only — proven OK here), fp32 accum/out.
// ---------------------------------------------------------------------------
#define SPMM_BODY_HF(j)                                                     \
    {                                                                       \
        int2  m = es[w][(j)];                                               \
        float v = __int_as_float(m.y);                                      \
        uint2 u = __ldg(d2 + (size_t)m.x * 32 + lane);                      \
        __half2 h0 = *reinterpret_cast<__half2*>(&u.x);                     \
        __half2 h1 = *reinterpret_cast<__half2*>(&u.y);                     \
        float2 f0 = __half22float2(h0);                                     \
        float2 f1 = __half22float2(h1);                                     \
        acc.x = fmaf(v, f0.x, acc.x);                                       \
        acc.y = fmaf(v, f0.y, acc.y);                                       \
        acc.z = fmaf(v, f1.x, acc.z);                                       \
        acc.w = fmaf(v, f1.y, acc.w);                                       \
    }

__global__ void k_spmm_hf(const int* __restrict__ rp, const int2* __restrict__ ed,
                          const __half* __restrict__ dense, float* __restrict__ out,
                          int nrows) {
    __shared__ int2 es[8][32];
    int wrow = (blockIdx.x * blockDim.x + threadIdx.x) >> 5;
    if (wrow >= nrows) return;
    int lane = threadIdx.x & 31;
    int w = (threadIdx.x >> 5) & 7;
    int start = __ldg(rp + wrow);
    int end   = __ldg(rp + wrow + 1);

    const uint2* d2 = reinterpret_cast<const uint2*>(dense);
    float4 acc = make_float4(0.f, 0.f, 0.f, 0.f);

    for (int base = start; base < end; base += 32) {
        int idx = base + lane;
        es[w][lane] = (idx < end) ? __ldg(ed + idx) : make_int2(0, 0);
        __syncwarp();
        int cnt = end - base;
        if (cnt >= 32) {
            #pragma unroll
            for (int j = 0; j < 32; j++) SPMM_BODY_HF(j)
        } else {
            for (int j = 0; j < cnt; j++) SPMM_BODY_HF(j)
        }
        __syncwarp();
    }
    reinterpret_cast<float4*>(out)[(size_t)wrow * 32 + lane] = acc;
}

// ---------------------------------------------------------------------------
// Plain GEMM: out = X @ W^T (fp32 out), f32x2 packed, 64-row tiles.
// ---------------------------------------------------------------------------
#define GEMM_BR 64
#define WPAD 130
#define XPAD 129

__global__ void k_gemm(const float* __restrict__ X, const float* __restrict__ W,
                       float* __restrict__ out, int R) {
    extern __shared__ float sm[];
    float* Wt = sm;                   // [128][WPAD], k-major
    float* Xs = sm + 128 * WPAD;      // [64][XPAD]
    int tid = threadIdx.x;

    for (int i = tid; i < 128 * 128; i += 256) {
        int c = i >> 7, k = i & 127;
        Wt[k * WPAD + c] = W[i];
    }
    int rb = blockIdx.x * GEMM_BR;
    for (int i = tid; i < GEMM_BR * 128; i += 256) {
        int r = i >> 7, k = i & 127;
        int gr = rb + r;
        Xs[r * XPAD + k] = (gr < R) ? X[(size_t)gr * HD + k] : 0.f;
    }
    __syncthreads();

    int tx = tid & 15, ty = tid >> 4;
    int r0 = ty * 4;
    int c0 = tx * 8;
    ull acc[4][4];
    #pragma unroll
    for (int i = 0; i < 4; i++)
        #pragma unroll
        for (int j = 0; j < 4; j++) acc[i][j] = 0ull;

    #pragma unroll 2
    for (int k = 0; k < 128; k++) {
        ull wv[4];
        #pragma unroll
        for (int jp = 0; jp < 4; jp++)
            wv[jp] = *reinterpret_cast<const ull*>(&Wt[k * WPAD + c0 + 2 * jp]);
        #pragma unroll
        for (int i = 0; i < 4; i++) {
            float xs = Xs[(r0 + i) * XPAD + k];
            ull xx;
            PACK2(xx, xs);
            #pragma unroll
            for (int jp = 0; jp < 4; jp++)
                FFMA2(acc[i][jp], xx, wv[jp], acc[i][jp]);
        }
    }

    #pragma unroll
    for (int i = 0; i < 4; i++) {
        int gr = rb + r0 + i;
        if (gr >= R) continue;
        float v[8];
        #pragma unroll
        for (int jp = 0; jp < 4; jp++) UNPACK2(v[2 * jp], v[2 * jp + 1], acc[i][jp]);
        float4* op = reinterpret_cast<float4*>(out + (size_t)gr * HD + c0);
        op[0] = make_float4(v[0], v[1], v[2], v[3]);
        op[1] = make_float4(v[4], v[5], v[6], v[7]);
    }
}

// ---------------------------------------------------------------------------
// head: logits = relu(doc @ mlpW^T + mlpb) @ clfW^T + clfb   (f32x2 packed)
// ---------------------------------------------------------------------------
#define HPAD 130
__global__ void k_head(const float* __restrict__ doc, const float* __restrict__ mlpW,
                       const float* __restrict__ mlpb, const float* __restrict__ clfW,
                       const float* __restrict__ clfb, float* __restrict__ out) {
    extern __shared__ float sm[];
    float* Ws = sm;                       // [128][130]
    float* xs = Ws + 128 * HPAD;          // [128]
    float* mb = xs + 128;
    float* c0 = mb + 128;
    float* c1 = c0 + 128;
    __shared__ float red0[4], red1[4];

    int tid = threadIdx.x;
    for (int i = tid; i < 128 * 128; i += 128) {
        int r = i >> 7, k = i & 127;
        Ws[r * HPAD + k] = mlpW[i];
    }
    mb[tid] = mlpb[tid];
    c0[tid] = clfW[tid];
    c1[tid] = clfW[128 + tid];
    float cb0 = clfb[0], cb1 = clfb[1];
    __syncthreads();

    int lane = tid & 31, wid = tid >> 5;
    const ull* wrow = reinterpret_cast<const ull*>(&Ws[tid * HPAD]);
    for (int d = blockIdx.x; d < N_DOCS; d += gridDim.x) {
        xs[tid] = doc[(size_t)d * HD + tid];
        __syncthreads();
        ull acc2 = 0ull;
        const ull* x2 = reinterpret_cast<const ull*>(xs);
        #pragma unroll 8
        for (int kp = 0; kp < 64; kp++)
            FFMA2(acc2, x2[kp], wrow[kp], acc2);
        float alo, ahi;
        UNPACK2(alo, ahi, acc2);
        float h = fmaxf(alo + ahi + mb[tid], 0.f);
        float p0 = h * c0[tid];
        float p1 = h * c1[tid];
        #pragma unroll
        for (int o = 16; o; o >>= 1) {
            p0 += __shfl_down_sync(0xFFFFFFFFu, p0, o);
            p1 += __shfl_down_sync(0xFFFFFFFFu, p1, o);
        }
        if (lane == 0) { red0[wid] = p0; red1[wid] = p1; }
        __syncthreads();
        if (tid == 0) out[(size_t)d * 2]     = red0[0] + red0[1] + red0[2] + red0[3] + cb0;
        if (tid == 1) out[(size_t)d * 2 + 1] = red1[0] + red1[1] + red1[2] + red1[3] + cb1;
        __syncthreads();
    }
}

// ---------------------------------------------------------------------------
extern "C" void kernel_launch(void* const* d_in, const int* in_sizes, int n_in,
                              void* d_out, int out_size) {
    const int*   A_row  = (const int*)  d_in[0];
    const int*   A_col  = (const int*)  d_in[1];
    const float* A_val  = (const float*)d_in[2];
    const int*   X_row  = (const int*)  d_in[3];
    const int*   X_col  = (const int*)  d_in[4];
    const float* X_val  = (const float*)d_in[5];
    const float* emb_W  = (const float*)d_in[6];
    const float* lin1_W = (const float*)d_in[7];
    const float* lin2_W = (const float*)d_in[8];
    const float* norm_g = (const float*)d_in[9];
    const float* norm_b = (const float*)d_in[10];
    const float* mlp_W  = (const float*)d_in[11];
    const float* mlp_b  = (const float*)d_in[12];
    const float* clf_W  = (const float*)d_in[13];
    const float* clf_b  = (const float*)d_in[14];
    float* out = (float*)d_out;

    int E   = in_sizes[0];
    int NNZ = in_sizes[3];

    void *pb1, *pb2, *pSh, *pdoc, *pAed, *pXed, *pArp, *pAwp, *pAcnt, *pXrp, *pXwp, *pXcnt;
    cudaGetSymbolAddress(&pb1, g_buf1);
    cudaGetSymbolAddress(&pb2, g_buf2);
    cudaGetSymbolAddress(&pSh, g_Sh);
    cudaGetSymbolAddress(&pdoc, g_doc);
    cudaGetSymbolAddress(&pAed, g_Aed);
    cudaGetSymbolAddress(&pXed, g_Xed);
    cudaGetSymbolAddress(&pArp, g_Arp);
    cudaGetSymbolAddress(&pAwp, g_Awp);
    cudaGetSymbolAddress(&pAcnt, g_Acnt);
    cudaGetSymbolAddress(&pXrp, g_Xrp);
    cudaGetSymbolAddress(&pXwp, g_Xwp);
    cudaGetSymbolAddress(&pXcnt, g_Xcnt);
    float*  b1  = (float*)pb1;
    float*  b2  = (float*)pb2;
    __half* Sh  = (__half*)pSh;
    float*  bd  = (float*)pdoc;
    int2* Aed = (int2*)pAed;
    int2* Xed = (int2*)pXed;
    int *Arp = (int*)pArp, *Awp = (int*)pAwp, *Acnt = (int*)pAcnt;
    int *Xrp = (int*)pXrp, *Xwp = (int*)pXwp, *Xcnt = (int*)pXcnt;

    const int gemm_smem = (128 * WPAD + GEMM_BR * XPAD) * sizeof(float);
    const int head_smem = (128 * HPAD + 4 * 128) * sizeof(float);
    cudaFuncSetAttribute(k_gemm, cudaFuncAttributeMaxDynamicSharedMemorySize, gemm_smem);
    cudaFuncSetAttribute(k_head, cudaFuncAttributeMaxDynamicSharedMemorySize, head_smem);

    // side stream for gemm1 overlap with CSR build (created once)
    static cudaStream_t s2 = nullptr;
    static cudaEvent_t evRoot = nullptr, evE1 = nullptr;
    if (!s2) {
        cudaStreamCreateWithFlags(&s2, cudaStreamNonBlocking);
        cudaEventCreateWithFlags(&evRoot, cudaEventDisableTiming);
        cudaEventCreateWithFlags(&evE1,   cudaEventDisableTiming);
    }
    cudaStream_t s0 = 0;

    const int nA4 = (E + 3) >> 2;
    const int nX4 = (NNZ + 3) >> 2;
    const int qg = (nA4 + nX4 + 255) / 256;
    const int spmmA_grid = (V_WORDS * 32 + 255) / 256;
    const int spmmX_grid = (N_DOCS * 32 + 255) / 256;
    const int gemm_grid  = (V_WORDS + GEMM_BR - 1) / GEMM_BR;

    // fork: E1 = emb @ lin1^T on side stream (independent of CSR build)
    cudaEventRecord(evRoot, s0);
    cudaStreamWaitEvent(s2, evRoot, 0);
    k_gemm<<<gemm_grid, 256, gemm_smem, s2>>>(emb_W, lin1_W, b1, V_WORDS);
    cudaEventRecord(evE1, s2);

    // --- CSR builds on main stream (4 edges/thread hist & scatter) ---
    k_zero2<<<(V_WORDS + N_DOCS + 255) / 256, 256, 0, s0>>>(Acnt, V_WORDS, Xcnt, N_DOCS);
    k_hist2<<<qg, 256, 0, s0>>>(A_row, Acnt, nA4, E, X_row, Xcnt, NNZ);
    k_scan2<<<2, 1024, 0, s0>>>(Acnt, Arp, Awp, V_WORDS, Xcnt, Xrp, Xwp, N_DOCS);
    k_scatter2<<<qg, 256, 0, s0>>>(A_row, A_col, A_val, Awp, Aed, nA4, E,
                                   X_row, X_col, X_val, Xwp, Xed, NNZ);

    // join, then H1 = relu(A @ E1)   (fp32 gather)
    cudaStreamWaitEvent(s0, evE1, 0);
    k_spmm_f<1><<<spmmA_grid, 256, 0, s0>>>(Arp, Aed, b1, b2, nullptr, V_WORDS,
                                            nullptr, nullptr, nullptr);
    // T2 = H1 @ lin2^T   (fp32)
    k_gemm<<<gemm_grid, 256, gemm_smem, s0>>>(b2, lin2_W, b1, V_WORDS);
    // Sh = fp16( LN(0.3*emb + 0.7*relu(A @ T2))*g + b + emb )
    k_spmm_f<2><<<spmmA_grid, 256, 0, s0>>>(Arp, Aed, b1, nullptr, Sh, V_WORDS,
                                            emb_W, norm_g, norm_b);
    // doc = X @ Sh       (fp16 gather, fp32 accum)
    k_spmm_hf<<<spmmX_grid, 256, 0, s0>>>(Xrp, Xed, Sh, bd, N_DOCS);
    // logits
    k_head<<<2000, 128, head_smem, 0>>>(bd, mlp_W, mlp_b, clf_W, clf_b, out);
}